// round 17
// baseline (speedup 1.0000x reference)
#include <cuda_runtime.h>
#include <cstdint>

#define BNUM 4
#define HS 64
#define WS 64
#define HU 512
#define WU 512
#define CORI 90
#define CMNT 180
#define COFF 8
#define KCAND 1024
#define NCELL (HS*WS)       // 4096
#define NPIX (HU*WU)        // 262144

// output layout (concatenated flattened returns):
// minut [4,1024,4] | keep [4,1024] | enh_vis [4,512,512] | mask_up*255 | ori_field
#define MINUT_OFF 0
#define KEEP_OFF  16384
#define ENH_OFF   20480
#define MASK_OFF  1069056
#define ORI_OFF   2117632

// -------- device scratch --------
__device__ float g_mask[BNUM*NCELL];
__device__ float g_er[BNUM*NCELL];
__device__ float g_tA[BNUM*NPIX];
__device__ float g_tB[BNUM*NPIX];
__device__ float g_maskup[BNUM*NPIX];
__device__ unsigned g_emin[BNUM];
__device__ unsigned g_emax[BNUM];

__device__ __forceinline__ unsigned f2ord(float f){
    unsigned u=__float_as_uint(f);
    return (u & 0x80000000u) ? ~u : (u | 0x80000000u);
}
__device__ __forceinline__ float ord2f(unsigned u){
    u = (u & 0x80000000u) ? (u & 0x7fffffffu) : ~u;
    return __uint_as_float(u);
}

// -------- small 5x5 opening on [B,64,64] (+ minmax init) --------
__global__ void small_erode(const float* __restrict__ seg){
    int i=blockIdx.x*blockDim.x+threadIdx.x;
    if(i<BNUM){ g_emin[i]=0xFFFFFFFFu; g_emax[i]=0u; }
    if(i>=BNUM*NCELL) return;
    int b=i/NCELL, cell=i%NCELL, r=cell/WS, c=cell%WS;
    const float* s=seg+(size_t)b*NCELL;
    int y0=r-2<0?0:r-2, y1=r+2>HS-1?HS-1:r+2;
    int x0=c-2<0?0:c-2, x1=c+2>WS-1?WS-1:c+2;
    float m=1e30f;
    for(int y=y0;y<=y1;y++)
        for(int x=x0;x<=x1;x++)
            m=fminf(m, rintf(s[y*WS+x]));
    g_er[i]=m;
}
__global__ void small_dilate(){
    int i=blockIdx.x*blockDim.x+threadIdx.x;
    if(i>=BNUM*NCELL) return;
    int b=i/NCELL, cell=i%NCELL, r=cell/WS, c=cell%WS;
    const float* s=g_er+(size_t)b*NCELL;
    int y0=r-2<0?0:r-2, y1=r+2>HS-1?HS-1:r+2;
    int x0=c-2<0?0:c-2, x1=c+2>WS-1?WS-1:c+2;
    float m=-1e30f;
    for(int y=y0;y<=y1;y++)
        for(int x=x0;x<=x1;x++)
            m=fmaxf(m, s[y*WS+x]);
    g_mask[i]=m;
}

// -------- horizontal brute pool helper (up4 HEAVY anchor) --------
__device__ __forceinline__ float poolH(const float* s, int y, int x, bool isMin){
    int a0=x-19; if(a0<0)a0=0;
    int a1=x+20; if(a1>WU-1)a1=WU-1;
    const float* row=s+(size_t)y*WU;
    float m = isMin?1e30f:-1e30f;
    for(int xx=a0;xx<=a1;xx++){
        float v=row[xx];
        m = isMin?fminf(m,v):fmaxf(m,v);
    }
    return m;
}
__global__ void up4_hmax(){
    int i=blockIdx.x*blockDim.x+threadIdx.x; if(i>=BNUM*NPIX)return;
    int b=i/NPIX, p=i%NPIX;
    g_maskup[i]=poolH(g_tA+(size_t)b*NPIX, p/WU, p%WU, false);
}

// -------- vmin as float4 vertical quad + rint (light, chain head) --------
__global__ void __launch_bounds__(256) up1_v4min(const float* __restrict__ segup){
    int i=blockIdx.x*256+threadIdx.x;
    if(i>=BNUM*NPIX/4) return;
    int b=i/(NPIX/4); int rem=i%(NPIX/4);
    int y=rem/(WU/4); int x0=(rem%(WU/4))*4;
    const float* base = segup + (size_t)b*NPIX + x0;
    float m0=1e30f, m1=1e30f, m2=1e30f, m3=1e30f;
    int a0=y-19; if(a0<0)a0=0;
    int a1=y+20; if(a1>HU-1)a1=HU-1;
    #pragma unroll 8
    for(int yy=a0;yy<=a1;yy++){
        float4 v=*reinterpret_cast<const float4*>(base+(size_t)yy*WU);
        m0=fminf(m0,rintf(v.x)); m1=fminf(m1,rintf(v.y));
        m2=fminf(m2,rintf(v.z)); m3=fminf(m3,rintf(v.w));
    }
    float4 o; o.x=m0; o.y=m1; o.z=m2; o.w=m3;
    *reinterpret_cast<float4*>(g_tA + (size_t)b*NPIX + (size_t)y*WU + x0) = o;
}

// -------- hmin as float4 OCT pool: 8 outputs/thread --------
// k = x - (x0-20); quads q=0..11 cover k=0..47; output j (j=0..7) needs k in [j+1, j+40].
// C = op(q2..q9) common. Extras per output from q0/q1/q10/q11 partials.
__global__ void __launch_bounds__(256) up2_h8min(){
    int i=blockIdx.x*256+threadIdx.x;
    if(i>=BNUM*NPIX/8) return;
    int b=i/(NPIX/8); int rem=i%(NPIX/8);
    int row=rem/(WU/8); int x0=(rem%(WU/8))*8;
    const float* rp = g_tA + (size_t)b*NPIX + (size_t)row*WU;
    const float NEU=1e30f;
    float qm[12];
    float q0e1,q0e2,q0e3;      // q0 elements k1,k2,k3
    float q1e1,q1e2,q1e3;      // q1 elements k5,k6,k7
    float q10e0,q10e1,q10e2;   // q10 elements k40,k41,k42
    float q11e0,q11e1,q11e2;   // q11 elements k44,k45,k46
    #pragma unroll
    for(int q=0;q<12;q++){
        int bs=x0-20+4*q;
        float a0,a1,a2,a3;
        if(bs>=0 && bs+3<WU){
            float4 v=*reinterpret_cast<const float4*>(rp+bs);
            a0=v.x; a1=v.y; a2=v.z; a3=v.w;
        } else {
            a0=(bs  >=0 && bs  <WU)? rp[bs  ] : NEU;
            a1=(bs+1>=0 && bs+1<WU)? rp[bs+1] : NEU;
            a2=(bs+2>=0 && bs+2<WU)? rp[bs+2] : NEU;
            a3=(bs+3>=0 && bs+3<WU)? rp[bs+3] : NEU;
        }
        if(q==0){ q0e1=a1; q0e2=a2; q0e3=a3; }
        if(q==1){ q1e1=a1; q1e2=a2; q1e3=a3; }
        if(q==10){ q10e0=a0; q10e1=a1; q10e2=a2; }
        if(q==11){ q11e0=a0; q11e1=a1; q11e2=a2; }
        qm[q]=fminf(fminf(a0,a1),fminf(a2,a3));
    }
    float C=qm[2];
    #pragma unroll
    for(int k=3;k<=9;k++) C=fminf(C,qm[k]);
    // partials
    float t3=q0e3, t2=fminf(q0e2,t3), t1=fminf(q0e1,t2);   // q0 suffixes (k1..3 / k2..3 / k3)
    float s3=q1e3, s2=fminf(q1e2,s3), s1=fminf(q1e1,s2);   // q1 suffixes (k5..7 / k6..7 / k7)
    float p1=q10e0, p2=fminf(p1,q10e1), p3=fminf(p2,q10e2);// q10 prefixes (k40 / k40..41 / k40..42)
    float u1=q11e0, u2=fminf(u1,q11e1), u3=fminf(u2,q11e2);// q11 prefixes
    float Cq1=fminf(C,qm[1]);
    float Cq10=fminf(C,qm[10]);
    float4 oA, oB;
    oA.x=fminf(Cq1,fminf(t1,p1));
    oA.y=fminf(Cq1,fminf(t2,p2));
    oA.z=fminf(Cq1,fminf(t3,p3));
    oA.w=fminf(Cq1,qm[10]);
    oB.x=fminf(Cq10,fminf(s1,u1));
    oB.y=fminf(Cq10,fminf(s2,u2));
    oB.z=fminf(Cq10,fminf(s3,u3));
    oB.w=fminf(Cq10,qm[11]);
    float* d=g_tB + (size_t)b*NPIX + (size_t)row*WU + x0;
    *reinterpret_cast<float4*>(d)   = oA;
    *reinterpret_cast<float4*>(d+4) = oB;
}

// -------- vmax as float4 vertical y-pair: 8 outputs/thread --------
// outputs (y0, y0+1) x (x0..x0+3); shared rows [y0-18, y0+20]; extras y0-19 (out0), y0+21 (out1)
__global__ void __launch_bounds__(256) up3_v8max(){
    int i=blockIdx.x*256+threadIdx.x;
    if(i>=BNUM*NPIX/8) return;
    int b=i/(NPIX/8); int rem=i%(NPIX/8);
    int yp=rem/(WU/4); int x0=(rem%(WU/4))*4;
    int y0=2*yp;
    const float* base = g_tB + (size_t)b*NPIX + x0;
    float c0=-1e30f, c1=-1e30f, c2=-1e30f, c3=-1e30f;   // shared core
    int a0=y0-18; if(a0<0)a0=0;
    int a1=y0+20; if(a1>HU-1)a1=HU-1;
    #pragma unroll 8
    for(int yy=a0;yy<=a1;yy++){
        float4 v=*reinterpret_cast<const float4*>(base+(size_t)yy*WU);
        c0=fmaxf(c0,v.x); c1=fmaxf(c1,v.y); c2=fmaxf(c2,v.z); c3=fmaxf(c3,v.w);
    }
    float4 o0; o0.x=c0; o0.y=c1; o0.z=c2; o0.w=c3;
    float4 o1=o0;
    if(y0-19>=0){
        float4 v=*reinterpret_cast<const float4*>(base+(size_t)(y0-19)*WU);
        o0.x=fmaxf(o0.x,v.x); o0.y=fmaxf(o0.y,v.y); o0.z=fmaxf(o0.z,v.z); o0.w=fmaxf(o0.w,v.w);
    }
    if(y0+21<=HU-1){
        float4 v=*reinterpret_cast<const float4*>(base+(size_t)(y0+21)*WU);
        o1.x=fmaxf(o1.x,v.x); o1.y=fmaxf(o1.y,v.y); o1.z=fmaxf(o1.z,v.z); o1.w=fmaxf(o1.w,v.w);
    }
    float* d=g_tA + (size_t)b*NPIX + (size_t)y0*WU + x0;
    *reinterpret_cast<float4*>(d)    = o0;
    *reinterpret_cast<float4*>(d+WU) = o1;
}

// -------- enhanced min/max per batch --------
__global__ void enh_minmax(const float* __restrict__ enh){
    int b=blockIdx.y;
    const float* e=enh+(size_t)b*NPIX;
    const float* m=g_maskup+(size_t)b*NPIX;
    float mn=1e30f, mx=-1e30f;
    for(int p=blockIdx.x*blockDim.x+threadIdx.x; p<NPIX; p+=gridDim.x*blockDim.x){
        float v=e[p]*m[p];
        mn=fminf(mn,v); mx=fmaxf(mx,v);
    }
    for(int o=16;o;o>>=1){
        mn=fminf(mn,__shfl_down_sync(0xFFFFFFFFu,mn,o));
        mx=fmaxf(mx,__shfl_down_sync(0xFFFFFFFFu,mx,o));
    }
    __shared__ float smn[8], smx[8];
    int lane=threadIdx.x&31, w=threadIdx.x>>5;
    if(lane==0){ smn[w]=mn; smx[w]=mx; }
    __syncthreads();
    if(threadIdx.x==0){
        int nw=blockDim.x>>5;
        for(int i=1;i<nw;i++){ mn=fminf(mn,smn[i]); mx=fmaxf(mx,smx[i]); }
        atomicMin(&g_emin[b], f2ord(mn));
        atomicMax(&g_emax[b], f2ord(mx));
    }
}

// -------- detect (top-k + NMS), one block per batch --------
__global__ void __launch_bounds__(1024) detect_nms(
    const float* __restrict__ mscore, const float* __restrict__ mori,
    const float* __restrict__ mxo,    const float* __restrict__ myo,
    float* __restrict__ out)
{
    int b=blockIdx.x, tid=threadIdx.x;
    __shared__ unsigned long long keys[4096];   // 32KB
    __shared__ int s_nv;
    float* sx=(float*)(keys+1024);
    float* sy=(float*)(keys+1536);
    float* sa=(float*)(keys+2048);
    unsigned char* skeep=(unsigned char*)(keys+2560);

    const float* sc=mscore+(size_t)b*NCELL;
    const float* mk=g_mask +(size_t)b*NCELL;

    bool anyv=false;
    for(int t=tid;t<NCELL;t+=1024){
        float v=sc[t]*mk[t];
        bool val = v>0.5f;
        anyv |= val;
        float mv = val ? v : -1.0f;
        keys[t] = ((unsigned long long)(~f2ord(mv))<<32) | (unsigned)t;
    }
    if(__syncthreads_count(anyv)==0){
        float* om=out + MINUT_OFF + (size_t)b*KCAND*4 + (size_t)tid*4;
        om[0]=0.0f; om[1]=0.0f; om[2]=0.0f; om[3]=0.0f;
        out[KEEP_OFF + (size_t)b*KCAND + tid]=0.0f;
        return;
    }

    for(int k=2;k<=4096;k<<=1){
        for(int j=k>>1;j>0;j>>=1){
            for(int i=tid;i<4096;i+=1024){
                int ixj=i^j;
                if(ixj>i){
                    unsigned long long a=keys[i], c=keys[ixj];
                    bool up=((i&k)==0);
                    if((a>c)==up){ keys[i]=c; keys[ixj]=a; }
                }
            }
            __syncthreads();
        }
    }

    unsigned long long key=keys[tid];
    int idx=(int)(key & 0xFFFFFFFFull);
    float score=sc[idx]*mk[idx];
    bool valid = score>0.5f;
    float xc=0.0f, yc=0.0f, ang=0.0f;
    if(!valid) score=0.0f;
    if(valid){
        int r=idx>>6, c=idx&63;
        const float* o=mori+(size_t)b*CMNT*NCELL+idx;
        int ai=0; float bv=o[0];
        for(int ch=1;ch<CMNT;ch++){ float v=o[(size_t)ch*NCELL]; if(v>bv){bv=v;ai=ch;} }
        const float* xo=mxo+(size_t)b*COFF*NCELL+idx;
        int xi=0; float bx=xo[0];
        for(int ch=1;ch<COFF;ch++){ float v=xo[(size_t)ch*NCELL]; if(v>bx){bx=v;xi=ch;} }
        const float* yo=myo+(size_t)b*COFF*NCELL+idx;
        int yi=0; float by=yo[0];
        for(int ch=1;ch<COFF;ch++){ float v=yo[(size_t)ch*NCELL]; if(v>by){by=v;yi=ch;} }
        ang=((float)ai*2.0f-89.0f)*0.017453292519943295f;
        xc=(float)c*8.0f+(float)xi;
        yc=(float)r*8.0f+(float)yi;
    }
    if(tid==0) s_nv=0;
    __syncthreads();
    sx[tid]=xc; sy[tid]=yc; sa[tid]=ang; skeep[tid]=valid?1:0;
    atomicMax(&s_nv, valid?(tid+1):0);
    __syncthreads();
    int nv=s_nv;
    for(int i=0;i<nv;i++){
        if(skeep[i] && tid>i && skeep[tid]){
            float dx=sx[tid]-sx[i], dy=sy[tid]-sy[i];
            float d=sqrtf(dx*dx+dy*dy);
            float da=fabsf(sa[tid]-sa[i]);
            da=fminf(da, 6.2831853071795864f-da);
            if(d<16.0f && da<0.52359877559829887f) skeep[tid]=0;
        }
        __syncthreads();
    }
    float kf = skeep[tid]?1.0f:0.0f;
    float* om=out + MINUT_OFF + (size_t)b*KCAND*4 + (size_t)tid*4;
    om[0]=kf*xc; om[1]=kf*yc; om[2]=kf*ang; om[3]=kf*score;
    out[KEEP_OFF + (size_t)b*KCAND + tid]=kf;
}

// -------- finalize (float4): enh_vis, mask*255, ori_field; 4 pixels/thread --------
__global__ void __launch_bounds__(256) finalize4(const float* __restrict__ enh,
                         const float* __restrict__ oriup, float* __restrict__ out){
    int i=blockIdx.x*256+threadIdx.x;
    if(i>=BNUM*NPIX/4) return;
    int b=i/(NPIX/4); int rem=i%(NPIX/4);
    size_t off=(size_t)b*NPIX + (size_t)rem*4;
    size_t p=(size_t)rem*4;
    float4 m4=*reinterpret_cast<const float4*>(g_maskup+off);
    float4 e4=*reinterpret_cast<const float4*>(enh+off);
    float4 mk; mk.x=m4.x*255.0f; mk.y=m4.y*255.0f; mk.z=m4.z*255.0f; mk.w=m4.w*255.0f;
    *reinterpret_cast<float4*>(out+MASK_OFF+off)=mk;
    float emin=ord2f(g_emin[b]);
    float emax=ord2f(g_emax[b]);
    float inv=255.0f/(emax-emin+1e-8f);
    float4 ev;
    ev.x=(e4.x*m4.x-emin)*inv; ev.y=(e4.y*m4.y-emin)*inv;
    ev.z=(e4.z*m4.z-emin)*inv; ev.w=(e4.w*m4.w-emin)*inv;
    *reinterpret_cast<float4*>(out+ENH_OFF+off)=ev;
    float4 of; of.x=0.0f; of.y=0.0f; of.z=0.0f; of.w=0.0f;
    float* ofp=&of.x;
    const float* mp=&m4.x;
    const float* ob=oriup+(size_t)b*CORI*NPIX;
    #pragma unroll
    for(int k=0;k<4;k++){
        float m=mp[k];
        if(m!=0.0f){
            const float* o=ob+p+k;
            int ai=0; float bv=o[0];
            for(int ch=1;ch<CORI;ch++){ float v=o[(size_t)ch*NPIX]; if(v>bv){bv=v;ai=ch;} }
            ofp[k]=((float)ai*2.0f-90.0f)*0.017453292519943295f*m;
        }
    }
    *reinterpret_cast<float4*>(out+ORI_OFF+off)=of;
}

extern "C" void kernel_launch(void* const* d_in, const int* in_sizes, int n_in,
                              void* d_out, int out_size){
    const float* seg    =(const float*)d_in[0];
    const float* segup  =(const float*)d_in[1];
    const float* oriup  =(const float*)d_in[2];
    const float* enh    =(const float*)d_in[3];
    const float* mscore =(const float*)d_in[4];
    const float* mori   =(const float*)d_in[5];
    const float* mxo    =(const float*)d_in[6];
    const float* myo    =(const float*)d_in[7];
    float* out=(float*)d_out;

    int nSmall=(BNUM*NCELL+255)/256;
    int nBig  =(BNUM*NPIX +255)/256;
    int nVec  =(BNUM*NPIX/4+255)/256;   // 1024 blocks
    int nOct  =(BNUM*NPIX/8+255)/256;   // 512 blocks

    small_erode<<<nSmall,256>>>(seg);    // includes minmax init
    small_dilate<<<nSmall,256>>>();

    up1_v4min<<<nVec,256>>>(segup);      // light
    up2_h8min<<<nOct,256>>>();           // light (8 outputs/thread, new)
    up3_v8max<<<nOct,256>>>();           // light (8 outputs/thread, new)
    up4_hmax<<<nBig,256>>>();            // HEAVY anchor before detect

    {
        dim3 g(64,BNUM);
        enh_minmax<<<g,256>>>(enh);
    }

    detect_nms<<<BNUM,1024>>>(mscore, mori, mxo, myo, out);
    finalize4<<<nVec,256>>>(enh, oriup, out);
}